// round 6
// baseline (speedup 1.0000x reference)
#include <cuda_runtime.h>

#define NN 16000      // nodes
#define NE 256000     // edges
#define NT 640000     // triplets
#define NBATCH 128    // graphs
#define HD 64         // hidden
#define OUTD 32
#define TS 68         // smem row stride (floats): conflict-free for float4 LDS

// ---------------- device scratch ----------------
__device__ float g_Hh[NN * HD];      // h @ W1[0:64]
__device__ float g_P[NN * HD];       // h @ W2[0:64]
__device__ float g_R1[NN * HD];      // h @ Wn1[0:64]
__device__ float g_Rr3[3 * NN * HD]; // rbf[0:N] @ W1[64:70] + b1, all layers
__device__ float g_agg[NN * HD];     // triplet scatter (only rows < N matter)
__device__ float g_Q[NN * HD];       // agg @ W2[64:128] + b2
__device__ float g_aggr[NN * HD];    // edge accumulation onto nodes
__device__ float g_h[NN * HD];
__device__ int g_active[NT];
__device__ int g_cnt;
__device__ int g_deg[NN];
__device__ int g_off[NN + 1];
__device__ int g_cursor[NN];
__device__ int g_src_sorted[NE];
__device__ float g_pool[NBATCH * HD];
__device__ float g_gcnt[NBATCH];

__device__ __forceinline__ void red_add_v4(float* addr, float4 v) {
    asm volatile("red.global.add.v4.f32 [%0], {%1,%2,%3,%4};"
                 :: "l"(addr), "f"(v.x), "f"(v.y), "f"(v.z), "f"(v.w)
                 : "memory");
}

// ---------------- tiled GEMM building blocks ----------------
// A tile stored transposed in smem: As[k*TS + row]
__device__ __forceinline__ void load_A_global(float* As, const float* __restrict__ A,
                                              int row0, int t) {
    int r = t >> 2;             // 0..63
    int kb = (t & 3) * 16;      // 0,16,32,48
    const float4* src = (const float4*)(A + (row0 + r) * HD + kb);
#pragma unroll
    for (int i = 0; i < 4; i++) {
        float4 v = src[i];
        int k = kb + i * 4;
        As[(k + 0) * TS + r] = v.x;
        As[(k + 1) * TS + r] = v.y;
        As[(k + 2) * TS + r] = v.z;
        As[(k + 3) * TS + r] = v.w;
    }
}

__device__ __forceinline__ void load_W(float* Ws, const float* __restrict__ W, int t) {
    int k = t >> 2;
    int nb = (t & 3) * 16;
    const float4* src = (const float4*)(W + k * HD + nb);
    float4* dst = (float4*)(Ws + k * TS + nb);
#pragma unroll
    for (int i = 0; i < 4; i++) dst[i] = src[i];
}

__device__ __forceinline__ void mm64(const float* As, const float* Ws,
                                     float4 c[4], int ri, int ci) {
#pragma unroll 8
    for (int k = 0; k < 64; k++) {
        float4 a = *(const float4*)(As + k * TS + ri * 4);
        float4 b = *(const float4*)(Ws + k * TS + ci * 4);
        c[0].x = fmaf(a.x, b.x, c[0].x); c[0].y = fmaf(a.x, b.y, c[0].y);
        c[0].z = fmaf(a.x, b.z, c[0].z); c[0].w = fmaf(a.x, b.w, c[0].w);
        c[1].x = fmaf(a.y, b.x, c[1].x); c[1].y = fmaf(a.y, b.y, c[1].y);
        c[1].z = fmaf(a.y, b.z, c[1].z); c[1].w = fmaf(a.y, b.w, c[1].w);
        c[2].x = fmaf(a.z, b.x, c[2].x); c[2].y = fmaf(a.z, b.y, c[2].y);
        c[2].z = fmaf(a.z, b.z, c[2].z); c[2].w = fmaf(a.z, b.w, c[2].w);
        c[3].x = fmaf(a.w, b.x, c[3].x); c[3].y = fmaf(a.w, b.y, c[3].y);
        c[3].z = fmaf(a.w, b.z, c[3].z); c[3].w = fmaf(a.w, b.w, c[3].w);
    }
}

__device__ __forceinline__ void store_A_trans(float* As, const float4 c[4], int ri, int ci) {
#pragma unroll
    for (int i = 0; i < 4; i++) {
        int r = ri * 4 + i;
        As[(ci * 4 + 0) * TS + r] = c[i].x;
        As[(ci * 4 + 1) * TS + r] = c[i].y;
        As[(ci * 4 + 2) * TS + r] = c[i].z;
        As[(ci * 4 + 3) * TS + r] = c[i].w;
    }
}

// ---------------- setup ----------------
__global__ void zero_init_kernel() {
    int i = blockIdx.x * blockDim.x + threadIdx.x;
    if (i < NN * HD / 4) ((float4*)g_agg)[i] = make_float4(0.f, 0.f, 0.f, 0.f);
    if (i < NN) g_deg[i] = 0;
    if (i < NBATCH * HD) g_pool[i] = 0.f;
    if (i < NBATCH) g_gcnt[i] = 0.f;
    if (i == 0) g_cnt = 0;
}

// compact active triplets + histogram edge dst degrees
__global__ void compact_hist_kernel(const int* __restrict__ j_idx,
                                    const int* __restrict__ ei) {
    int i = blockIdx.x * blockDim.x + threadIdx.x;
    if (i < NT) {
        if (j_idx[i] < NN) g_active[atomicAdd(&g_cnt, 1)] = i;
    }
    if (i < NE) {
        atomicAdd(&g_deg[ei[NE + i]], 1);
    }
}

// single-block exclusive scan of g_deg -> g_off, g_cursor
__global__ void scan_kernel() {
    __shared__ int s[1024];
    __shared__ int carry_s;
    int t = threadIdx.x;
    if (t == 0) carry_s = 0;
    __syncthreads();
    for (int chunk = 0; chunk < (NN + 1023) / 1024; chunk++) {
        int idx = chunk * 1024 + t;
        int v = (idx < NN) ? g_deg[idx] : 0;
        s[t] = v;
        __syncthreads();
#pragma unroll
        for (int off = 1; off < 1024; off <<= 1) {
            int x = (t >= off) ? s[t - off] : 0;
            __syncthreads();
            s[t] += x;
            __syncthreads();
        }
        int excl = carry_s + s[t] - v;
        if (idx < NN) {
            g_off[idx] = excl;
            g_cursor[idx] = excl;
        }
        __syncthreads();
        if (t == 0) carry_s += s[1023];
        __syncthreads();
    }
    if (t == 0) g_off[NN] = NE;
}

__global__ void scatter_kernel(const int* __restrict__ ei) {
    int e = blockIdx.x * blockDim.x + threadIdx.x;
    if (e < NE) {
        int d = ei[NE + e];
        int pos = atomicAdd(&g_cursor[d], 1);
        g_src_sorted[pos] = ei[e];
    }
}

// ---------------- Rr for all 3 layers in one launch ----------------
// grid: (NN/16, 3), block 256; thread -> (node, float4 col)
__global__ void rbfproj_all_kernel(const float* __restrict__ rbf,
                                   const float* __restrict__ W1,
                                   const float* __restrict__ b1) {
    __shared__ float Wc[6 * HD];
    __shared__ float bs[HD];
    int l = blockIdx.y;
    int t = threadIdx.x;
    const float* W = W1 + l * 76 * HD + 64 * HD;
    for (int i = t; i < 6 * HD / 4; i += blockDim.x)
        ((float4*)Wc)[i] = ((const float4*)W)[i];
    if (t < HD) bs[t] = b1[l * HD + t];
    __syncthreads();
    int node = blockIdx.x * 16 + (t >> 4);
    int c4 = t & 15;
    if (node >= NN) return;
    float4 acc = ((float4*)bs)[c4];
    const float* r = rbf + node * 6;
#pragma unroll
    for (int k = 0; k < 6; k++) {
        float v = r[k];
        float4 w = ((float4*)(Wc + k * HD))[c4];
        acc.x = fmaf(v, w.x, acc.x);
        acc.y = fmaf(v, w.y, acc.y);
        acc.z = fmaf(v, w.z, acc.z);
        acc.w = fmaf(v, w.w, acc.w);
    }
    ((float4*)(g_Rr3 + l * NN * HD + node * HD))[c4] = acc;
}

// ---------------- initial projection from x: Hh, P, R1 (layer 0) ----------------
__global__ void proj3_kernel(const float* __restrict__ in,
                             const float* __restrict__ Wa,
                             const float* __restrict__ Wb,
                             const float* __restrict__ Wc) {
    __shared__ float As[64 * TS];
    __shared__ float Ws[64 * TS];
    int t = threadIdx.x;
    int row0 = blockIdx.x * 64;
    load_A_global(As, in, row0, t);
    int ri = t >> 4, ci = t & 15;
    const float* Wl[3] = {Wa, Wb, Wc};
    float* Ol[3] = {g_Hh, g_P, g_R1};
    for (int s = 0; s < 3; s++) {
        __syncthreads();
        load_W(Ws, Wl[s], t);
        __syncthreads();
        float4 c[4];
        c[0] = c[1] = c[2] = c[3] = make_float4(0.f, 0.f, 0.f, 0.f);
        mm64(As, Ws, c, ri, ci);
        float* out = Ol[s];
#pragma unroll
        for (int i = 0; i < 4; i++)
            *(float4*)(out + (row0 + ri * 4 + i) * HD + ci * 4) = c[i];
    }
}

// ---------------- Q = agg @ W2b + b2 ; self-zero g_agg for next layer ----------------
__global__ void qproj_kernel(const float* __restrict__ W, const float* __restrict__ bias) {
    __shared__ float As[64 * TS];
    __shared__ float Ws[64 * TS];
    __shared__ float bs[HD];
    int t = threadIdx.x;
    int row0 = blockIdx.x * 64;
    load_A_global(As, g_agg, row0, t);
    // re-zero exactly the elements this thread just loaded (no cross-thread hazard)
    {
        int r = t >> 2;
        int kb = (t & 3) * 16;
        float4* dst = (float4*)(g_agg + (row0 + r) * HD + kb);
        float4 z = make_float4(0.f, 0.f, 0.f, 0.f);
#pragma unroll
        for (int i = 0; i < 4; i++) dst[i] = z;
    }
    load_W(Ws, W, t);
    if (t < HD) bs[t] = bias[t];
    __syncthreads();
    int ri = t >> 4, ci = t & 15;
    float4 bv = *(float4*)(bs + ci * 4);
    float4 c[4] = {bv, bv, bv, bv};
    mm64(As, Ws, c, ri, ci);
#pragma unroll
    for (int i = 0; i < 4; i++)
        *(float4*)(g_Q + (row0 + ri * 4 + i) * HD + ci * 4) = c[i];
}

// ---------------- fused node update: z -> h -> (optionally) next-layer projections ----------------
__global__ void node_update_kernel(const float* __restrict__ Wn1b, const float* __restrict__ bn1,
                                   const float* __restrict__ Wn2, const float* __restrict__ bn2,
                                   const float* __restrict__ W1a, const float* __restrict__ W2a,
                                   const float* __restrict__ Wn1a, int do_proj) {
    __shared__ float As[64 * TS];
    __shared__ float Ws[64 * TS];
    __shared__ float bs[HD];
    int t = threadIdx.x;
    int row0 = blockIdx.x * 64;
    int ri = t >> 4, ci = t & 15;

    // GEMM1: z = relu(R1 + aggr @ Wn1b + bn1)
    load_A_global(As, g_aggr, row0, t);
    load_W(Ws, Wn1b, t);
    if (t < HD) bs[t] = bn1[t];
    __syncthreads();
    float4 bv = *(float4*)(bs + ci * 4);
    float4 c[4] = {bv, bv, bv, bv};
    mm64(As, Ws, c, ri, ci);
#pragma unroll
    for (int i = 0; i < 4; i++) {
        float4 r = *(const float4*)(g_R1 + (row0 + ri * 4 + i) * HD + ci * 4);
        c[i].x = fmaxf(c[i].x + r.x, 0.f);
        c[i].y = fmaxf(c[i].y + r.y, 0.f);
        c[i].z = fmaxf(c[i].z + r.z, 0.f);
        c[i].w = fmaxf(c[i].w + r.w, 0.f);
    }
    __syncthreads();                 // all reads of As/Ws done
    store_A_trans(As, c, ri, ci);    // As = z
    load_W(Ws, Wn2, t);
    if (t < HD) bs[t] = bn2[t];
    __syncthreads();

    // GEMM2: h = z @ Wn2 + bn2
    bv = *(float4*)(bs + ci * 4);
    c[0] = c[1] = c[2] = c[3] = bv;
    mm64(As, Ws, c, ri, ci);
#pragma unroll
    for (int i = 0; i < 4; i++)
        *(float4*)(g_h + (row0 + ri * 4 + i) * HD + ci * 4) = c[i];

    if (!do_proj) return;

    __syncthreads();                 // GEMM2 reads of As/Ws done
    store_A_trans(As, c, ri, ci);    // As = h
    const float* Wl[3] = {W1a, W2a, Wn1a};
    float* Ol[3] = {g_Hh, g_P, g_R1};
    for (int s = 0; s < 3; s++) {
        load_W(Ws, Wl[s], t);
        __syncthreads();
        float4 d[4];
        d[0] = d[1] = d[2] = d[3] = make_float4(0.f, 0.f, 0.f, 0.f);
        mm64(As, Ws, d, ri, ci);
        float* out = Ol[s];
#pragma unroll
        for (int i = 0; i < 4; i++)
            *(float4*)(out + (row0 + ri * 4 + i) * HD + ci * 4) = d[i];
        __syncthreads();             // before next load_W overwrites Ws
    }
}

// ---------------- triplet stage: only active (j_idx < N) triplets ----------------
__global__ void triplet_kernel(const float* __restrict__ cbf,
                               const int* __restrict__ k_idx,
                               const int* __restrict__ j_idx,
                               const float* __restrict__ W1, int l) {
    __shared__ float Wc[6 * HD];
    int t = threadIdx.x;
    const float* W1c = W1 + l * 76 * HD + 70 * HD;
    for (int i = t; i < 6 * HD / 4; i += blockDim.x)
        ((float4*)Wc)[i] = ((const float4*)W1c)[i];
    __syncthreads();

    const float* Rr = g_Rr3 + l * NN * HD;
    int cnt = g_cnt;
    int lane = t & 15;
    int group = (blockIdx.x * blockDim.x + t) >> 4;
    int ngroups = (gridDim.x * blockDim.x) >> 4;
    for (int i = group; i < cnt; i += ngroups) {
        int tr = g_active[i];
        int k = k_idx[tr];
        int j = j_idx[tr];
        float4 a = ((const float4*)(g_Hh + k * HD))[lane];
        float4 b = ((const float4*)(Rr + j * HD))[lane];
        a.x += b.x; a.y += b.y; a.z += b.z; a.w += b.w;
        const float* cb = cbf + tr * 6;
#pragma unroll
        for (int kk = 0; kk < 6; kk++) {
            float v = cb[kk];
            float4 w = ((const float4*)(Wc + kk * HD))[lane];
            a.x = fmaf(v, w.x, a.x);
            a.y = fmaf(v, w.y, a.y);
            a.z = fmaf(v, w.z, a.z);
            a.w = fmaf(v, w.w, a.w);
        }
        a.x = fmaxf(a.x, 0.f); a.y = fmaxf(a.y, 0.f);
        a.z = fmaxf(a.z, 0.f); a.w = fmaxf(a.w, 0.f);
        red_add_v4(g_agg + j * HD + lane * 4, a);
    }
}

// ---------------- edge stage (CSR): aggr[d] = sum_{e: dst=d} relu(P[src_e]+Q[d]) ----------------
__global__ void edge_sorted_kernel() {
    int t = blockIdx.x * blockDim.x + threadIdx.x;
    int lane = t & 15;
    int d = t >> 4;
    if (d >= NN) return;
    int beg = g_off[d];
    int end = g_off[d + 1];
    float4 q = ((const float4*)(g_Q + d * HD))[lane];
    float4 acc = make_float4(0.f, 0.f, 0.f, 0.f);
    int e = beg;
    // unroll by 2 for MLP
    for (; e + 1 < end; e += 2) {
        int s0 = g_src_sorted[e];
        int s1 = g_src_sorted[e + 1];
        float4 p0 = ((const float4*)(g_P + s0 * HD))[lane];
        float4 p1 = ((const float4*)(g_P + s1 * HD))[lane];
        acc.x += fmaxf(p0.x + q.x, 0.f) + fmaxf(p1.x + q.x, 0.f);
        acc.y += fmaxf(p0.y + q.y, 0.f) + fmaxf(p1.y + q.y, 0.f);
        acc.z += fmaxf(p0.z + q.z, 0.f) + fmaxf(p1.z + q.z, 0.f);
        acc.w += fmaxf(p0.w + q.w, 0.f) + fmaxf(p1.w + q.w, 0.f);
    }
    if (e < end) {
        int s0 = g_src_sorted[e];
        float4 p0 = ((const float4*)(g_P + s0 * HD))[lane];
        acc.x += fmaxf(p0.x + q.x, 0.f);
        acc.y += fmaxf(p0.y + q.y, 0.f);
        acc.z += fmaxf(p0.z + q.z, 0.f);
        acc.w += fmaxf(p0.w + q.w, 0.f);
    }
    ((float4*)(g_aggr + d * HD))[lane] = acc;
}

// ---------------- pooling ----------------
__global__ void pool_kernel(const int* __restrict__ batch) {
    int t = blockIdx.x * blockDim.x + threadIdx.x;
    int lane = t & 15;
    int n = t >> 4;
    if (n >= NN) return;
    int b = batch[n];
    float4 v = ((const float4*)(g_h + n * HD))[lane];
    red_add_v4(g_pool + b * HD + lane * 4, v);
    if (lane == 0) atomicAdd(&g_gcnt[b], 1.0f);
}

// ---------------- final small MLP ----------------
__global__ void final_kernel(const float* __restrict__ Wo1,
                             const float* __restrict__ bo1,
                             const float* __restrict__ Wo2,
                             const float* __restrict__ bo2,
                             float* __restrict__ out) {
    __shared__ float pooled[HD];
    __shared__ float t1[HD];
    int b = blockIdx.x;
    int t = threadIdx.x;  // 64 threads
    float cnt = fmaxf(g_gcnt[b], 1.0f);
    pooled[t] = fmaxf(g_pool[b * HD + t] / cnt, 0.f);
    __syncthreads();
    float acc = bo1[t];
#pragma unroll 8
    for (int k = 0; k < HD; k++) acc = fmaf(pooled[k], Wo1[k * HD + t], acc);
    t1[t] = fmaxf(acc, 0.f);
    __syncthreads();
    if (t < OUTD) {
        float a2 = bo2[t];
#pragma unroll 8
        for (int k = 0; k < HD; k++) a2 = fmaf(t1[k], Wo2[k * OUTD + t], a2);
        out[b * OUTD + t] = a2;
    }
}

// ---------------- host orchestration ----------------
extern "C" void kernel_launch(void* const* d_in, const int* in_sizes, int n_in,
                              void* d_out, int out_size) {
    (void)in_sizes; (void)n_in; (void)out_size;
    const float* x   = (const float*)d_in[0];
    const float* rbf = (const float*)d_in[1];
    const float* cbf = (const float*)d_in[2];
    const float* W1  = (const float*)d_in[3];
    const float* b1  = (const float*)d_in[4];
    const float* W2  = (const float*)d_in[5];
    const float* b2  = (const float*)d_in[6];
    const float* Wn1 = (const float*)d_in[7];
    const float* bn1 = (const float*)d_in[8];
    const float* Wn2 = (const float*)d_in[9];
    const float* bn2 = (const float*)d_in[10];
    const float* Wo1 = (const float*)d_in[11];
    const float* bo1 = (const float*)d_in[12];
    const float* Wo2 = (const float*)d_in[13];
    const float* bo2 = (const float*)d_in[14];
    const int* ei    = (const int*)d_in[15];
    const int* k_idx = (const int*)d_in[16];
    const int* j_idx = (const int*)d_in[17];
    const int* batch = (const int*)d_in[18];
    float* out = (float*)d_out;

    zero_init_kernel<<<(NN * HD / 4 + 255) / 256, 256>>>();
    compact_hist_kernel<<<(NT + 255) / 256, 256>>>(j_idx, ei);
    scan_kernel<<<1, 1024>>>();
    scatter_kernel<<<(NE + 255) / 256, 256>>>(ei);
    rbfproj_all_kernel<<<dim3(NN / 16, 3), 256>>>(rbf, W1, b1);
    proj3_kernel<<<NN / 64, 256>>>(x, W1, W2, Wn1);

    for (int l = 0; l < 3; l++) {
        triplet_kernel<<<1024, 256>>>(cbf, k_idx, j_idx, W1, l);
        qproj_kernel<<<NN / 64, 256>>>(W2 + l * 128 * HD + 64 * HD, b2 + l * HD);
        edge_sorted_kernel<<<(NN * 16 + 255) / 256, 256>>>();
        int nl = (l < 2) ? (l + 1) : l;
        node_update_kernel<<<NN / 64, 256>>>(
            Wn1 + l * 128 * HD + 64 * HD, bn1 + l * HD,
            Wn2 + l * 64 * HD, bn2 + l * HD,
            W1 + nl * 76 * HD, W2 + nl * 128 * HD, Wn1 + nl * 128 * HD,
            (l < 2) ? 1 : 0);
    }

    pool_kernel<<<(NN * 16 + 255) / 256, 256>>>(batch);
    final_kernel<<<NBATCH, 64>>>(Wo1, bo1, Wo2, bo2, out);
}

// round 8
// speedup vs baseline: 1.6005x; 1.6005x over previous
#include <cuda_runtime.h>

#define NN 16000      // nodes
#define NE 256000     // edges
#define NT 640000     // triplets
#define NBATCH 128    // graphs
#define HD 64         // hidden
#define OUTD 32
#define TS 68         // smem row stride (floats): conflict-free for float4 LDS

// ---------------- device scratch ----------------
__device__ float g_Hh[NN * HD];      // h @ W1[0:64]
__device__ float g_P[NN * HD];       // h @ W2[0:64]
__device__ float g_R1[NN * HD];      // h @ Wn1[0:64]
__device__ float g_Rr3[3 * NN * HD]; // rbf[0:N] @ W1[64:70] + b1, all layers
__device__ float g_agg[NN * HD];     // triplet scatter (only rows < N matter)
__device__ float g_Q[NN * HD];       // agg @ W2[64:128] + b2
__device__ float g_aggr[NN * HD];    // edge scatter onto nodes
__device__ float g_h[NN * HD];
__device__ int g_active[NT];
__device__ int g_cnt;
__device__ float g_pool[NBATCH * HD];
__device__ float g_gcnt[NBATCH];

__device__ __forceinline__ void red_add_v4(float* addr, float4 v) {
    asm volatile("red.global.add.v4.f32 [%0], {%1,%2,%3,%4};"
                 :: "l"(addr), "f"(v.x), "f"(v.y), "f"(v.z), "f"(v.w)
                 : "memory");
}

// ---------------- tiled GEMM building blocks ----------------
// A tile stored transposed in smem: As[k*TS + row]
__device__ __forceinline__ void load_A_global(float* As, const float* __restrict__ A,
                                              int row0, int t) {
    int r = t >> 2;             // 0..63
    int kb = (t & 3) * 16;      // 0,16,32,48
    const float4* src = (const float4*)(A + (row0 + r) * HD + kb);
#pragma unroll
    for (int i = 0; i < 4; i++) {
        float4 v = src[i];
        int k = kb + i * 4;
        As[(k + 0) * TS + r] = v.x;
        As[(k + 1) * TS + r] = v.y;
        As[(k + 2) * TS + r] = v.z;
        As[(k + 3) * TS + r] = v.w;
    }
}

__device__ __forceinline__ void load_W(float* Ws, const float* __restrict__ W, int t) {
    int k = t >> 2;
    int nb = (t & 3) * 16;
    const float4* src = (const float4*)(W + k * HD + nb);
    float4* dst = (float4*)(Ws + k * TS + nb);
#pragma unroll
    for (int i = 0; i < 4; i++) dst[i] = src[i];
}

__device__ __forceinline__ void mm64(const float* As, const float* Ws,
                                     float4 c[4], int ri, int ci) {
#pragma unroll 8
    for (int k = 0; k < 64; k++) {
        float4 a = *(const float4*)(As + k * TS + ri * 4);
        float4 b = *(const float4*)(Ws + k * TS + ci * 4);
        c[0].x = fmaf(a.x, b.x, c[0].x); c[0].y = fmaf(a.x, b.y, c[0].y);
        c[0].z = fmaf(a.x, b.z, c[0].z); c[0].w = fmaf(a.x, b.w, c[0].w);
        c[1].x = fmaf(a.y, b.x, c[1].x); c[1].y = fmaf(a.y, b.y, c[1].y);
        c[1].z = fmaf(a.y, b.z, c[1].z); c[1].w = fmaf(a.y, b.w, c[1].w);
        c[2].x = fmaf(a.z, b.x, c[2].x); c[2].y = fmaf(a.z, b.y, c[2].y);
        c[2].z = fmaf(a.z, b.z, c[2].z); c[2].w = fmaf(a.z, b.w, c[2].w);
        c[3].x = fmaf(a.w, b.x, c[3].x); c[3].y = fmaf(a.w, b.y, c[3].y);
        c[3].z = fmaf(a.w, b.z, c[3].z); c[3].w = fmaf(a.w, b.w, c[3].w);
    }
}

__device__ __forceinline__ void store_A_trans(float* As, const float4 c[4], int ri, int ci) {
#pragma unroll
    for (int i = 0; i < 4; i++) {
        int r = ri * 4 + i;
        As[(ci * 4 + 0) * TS + r] = c[i].x;
        As[(ci * 4 + 1) * TS + r] = c[i].y;
        As[(ci * 4 + 2) * TS + r] = c[i].z;
        As[(ci * 4 + 3) * TS + r] = c[i].w;
    }
}

// ---------------- setup ----------------
__global__ void zero_init_kernel() {
    int i = blockIdx.x * blockDim.x + threadIdx.x;
    if (i < NN * HD / 4) ((float4*)g_agg)[i] = make_float4(0.f, 0.f, 0.f, 0.f);
    if (i < NBATCH * HD) g_pool[i] = 0.f;
    if (i < NBATCH) g_gcnt[i] = 0.f;
    if (i == 0) g_cnt = 0;
}

__global__ void compact_kernel(const int* __restrict__ j_idx) {
    int i = blockIdx.x * blockDim.x + threadIdx.x;
    if (i < NT && j_idx[i] < NN) {
        g_active[atomicAdd(&g_cnt, 1)] = i;
    }
}

// ---------------- Rr for all 3 layers in one launch ----------------
// grid: (NN/16, 3), block 256; thread -> (node, float4 col)
__global__ void rbfproj_all_kernel(const float* __restrict__ rbf,
                                   const float* __restrict__ W1,
                                   const float* __restrict__ b1) {
    __shared__ float Wc[6 * HD];
    __shared__ float bs[HD];
    int l = blockIdx.y;
    int t = threadIdx.x;
    const float* W = W1 + l * 76 * HD + 64 * HD;
    for (int i = t; i < 6 * HD / 4; i += blockDim.x)
        ((float4*)Wc)[i] = ((const float4*)W)[i];
    if (t < HD) bs[t] = b1[l * HD + t];
    __syncthreads();
    int node = blockIdx.x * 16 + (t >> 4);
    int c4 = t & 15;
    if (node >= NN) return;
    float4 acc = ((float4*)bs)[c4];
    const float* r = rbf + node * 6;
#pragma unroll
    for (int k = 0; k < 6; k++) {
        float v = r[k];
        float4 w = ((float4*)(Wc + k * HD))[c4];
        acc.x = fmaf(v, w.x, acc.x);
        acc.y = fmaf(v, w.y, acc.y);
        acc.z = fmaf(v, w.z, acc.z);
        acc.w = fmaf(v, w.w, acc.w);
    }
    ((float4*)(g_Rr3 + l * NN * HD + node * HD))[c4] = acc;
}

// ---------------- initial projection from x: Hh, P, R1 (layer 0) ----------------
__global__ void proj3_kernel(const float* __restrict__ in,
                             const float* __restrict__ Wa,
                             const float* __restrict__ Wb,
                             const float* __restrict__ Wc) {
    __shared__ float As[64 * TS];
    __shared__ float Ws[64 * TS];
    int t = threadIdx.x;
    int row0 = blockIdx.x * 64;
    load_A_global(As, in, row0, t);
    int ri = t >> 4, ci = t & 15;
    const float* Wl[3] = {Wa, Wb, Wc};
    float* Ol[3] = {g_Hh, g_P, g_R1};
    for (int s = 0; s < 3; s++) {
        __syncthreads();
        load_W(Ws, Wl[s], t);
        __syncthreads();
        float4 c[4];
        c[0] = c[1] = c[2] = c[3] = make_float4(0.f, 0.f, 0.f, 0.f);
        mm64(As, Ws, c, ri, ci);
        float* out = Ol[s];
#pragma unroll
        for (int i = 0; i < 4; i++)
            *(float4*)(out + (row0 + ri * 4 + i) * HD + ci * 4) = c[i];
    }
}

// ---------------- Q = agg @ W2b + b2 ; self-zero g_agg; zero g_aggr rows ----------------
__global__ void qproj_kernel(const float* __restrict__ W, const float* __restrict__ bias) {
    __shared__ float As[64 * TS];
    __shared__ float Ws[64 * TS];
    __shared__ float bs[HD];
    int t = threadIdx.x;
    int row0 = blockIdx.x * 64;
    load_A_global(As, g_agg, row0, t);
    // re-zero exactly the elements this thread just loaded (no cross-thread hazard),
    // and zero this block's g_aggr rows before edge_kernel runs
    {
        int r = t >> 2;
        int kb = (t & 3) * 16;
        float4 z = make_float4(0.f, 0.f, 0.f, 0.f);
        float4* dst = (float4*)(g_agg + (row0 + r) * HD + kb);
        float4* dst2 = (float4*)(g_aggr + (row0 + r) * HD + kb);
#pragma unroll
        for (int i = 0; i < 4; i++) { dst[i] = z; dst2[i] = z; }
    }
    load_W(Ws, W, t);
    if (t < HD) bs[t] = bias[t];
    __syncthreads();
    int ri = t >> 4, ci = t & 15;
    float4 bv = *(float4*)(bs + ci * 4);
    float4 c[4] = {bv, bv, bv, bv};
    mm64(As, Ws, c, ri, ci);
#pragma unroll
    for (int i = 0; i < 4; i++)
        *(float4*)(g_Q + (row0 + ri * 4 + i) * HD + ci * 4) = c[i];
}

// ---------------- fused node update: z -> h -> (optionally) next-layer projections ----------------
__global__ void node_update_kernel(const float* __restrict__ Wn1b, const float* __restrict__ bn1,
                                   const float* __restrict__ Wn2, const float* __restrict__ bn2,
                                   const float* __restrict__ W1a, const float* __restrict__ W2a,
                                   const float* __restrict__ Wn1a, int do_proj) {
    __shared__ float As[64 * TS];
    __shared__ float Ws[64 * TS];
    __shared__ float bs[HD];
    int t = threadIdx.x;
    int row0 = blockIdx.x * 64;
    int ri = t >> 4, ci = t & 15;

    // GEMM1: z = relu(R1 + aggr @ Wn1b + bn1)
    load_A_global(As, g_aggr, row0, t);
    load_W(Ws, Wn1b, t);
    if (t < HD) bs[t] = bn1[t];
    __syncthreads();
    float4 bv = *(float4*)(bs + ci * 4);
    float4 c[4] = {bv, bv, bv, bv};
    mm64(As, Ws, c, ri, ci);
#pragma unroll
    for (int i = 0; i < 4; i++) {
        float4 r = *(const float4*)(g_R1 + (row0 + ri * 4 + i) * HD + ci * 4);
        c[i].x = fmaxf(c[i].x + r.x, 0.f);
        c[i].y = fmaxf(c[i].y + r.y, 0.f);
        c[i].z = fmaxf(c[i].z + r.z, 0.f);
        c[i].w = fmaxf(c[i].w + r.w, 0.f);
    }
    __syncthreads();                 // all reads of As/Ws done
    store_A_trans(As, c, ri, ci);    // As = z
    load_W(Ws, Wn2, t);
    if (t < HD) bs[t] = bn2[t];
    __syncthreads();

    // GEMM2: h = z @ Wn2 + bn2
    bv = *(float4*)(bs + ci * 4);
    c[0] = c[1] = c[2] = c[3] = bv;
    mm64(As, Ws, c, ri, ci);
#pragma unroll
    for (int i = 0; i < 4; i++)
        *(float4*)(g_h + (row0 + ri * 4 + i) * HD + ci * 4) = c[i];

    if (!do_proj) return;

    __syncthreads();                 // GEMM2 reads of As/Ws done
    store_A_trans(As, c, ri, ci);    // As = h
    const float* Wl[3] = {W1a, W2a, Wn1a};
    float* Ol[3] = {g_Hh, g_P, g_R1};
    for (int s = 0; s < 3; s++) {
        load_W(Ws, Wl[s], t);
        __syncthreads();
        float4 d[4];
        d[0] = d[1] = d[2] = d[3] = make_float4(0.f, 0.f, 0.f, 0.f);
        mm64(As, Ws, d, ri, ci);
        float* out = Ol[s];
#pragma unroll
        for (int i = 0; i < 4; i++)
            *(float4*)(out + (row0 + ri * 4 + i) * HD + ci * 4) = d[i];
        __syncthreads();             // before next load_W overwrites Ws
    }
}

// ---------------- triplet stage: only active (j_idx < N) triplets ----------------
__global__ void triplet_kernel(const float* __restrict__ cbf,
                               const int* __restrict__ k_idx,
                               const int* __restrict__ j_idx,
                               const float* __restrict__ W1, int l) {
    __shared__ float Wc[6 * HD];
    int t = threadIdx.x;
    const float* W1c = W1 + l * 76 * HD + 70 * HD;
    for (int i = t; i < 6 * HD / 4; i += blockDim.x)
        ((float4*)Wc)[i] = ((const float4*)W1c)[i];
    __syncthreads();

    const float* Rr = g_Rr3 + l * NN * HD;
    int cnt = g_cnt;
    int lane = t & 15;
    int group = (blockIdx.x * blockDim.x + t) >> 4;
    int ngroups = (gridDim.x * blockDim.x) >> 4;
    for (int i = group; i < cnt; i += ngroups) {
        int tr = g_active[i];
        int k = k_idx[tr];
        int j = j_idx[tr];
        float4 a = ((const float4*)(g_Hh + k * HD))[lane];
        float4 b = ((const float4*)(Rr + j * HD))[lane];
        a.x += b.x; a.y += b.y; a.z += b.z; a.w += b.w;
        const float* cb = cbf + tr * 6;
#pragma unroll
        for (int kk = 0; kk < 6; kk++) {
            float v = cb[kk];
            float4 w = ((const float4*)(Wc + kk * HD))[lane];
            a.x = fmaf(v, w.x, a.x);
            a.y = fmaf(v, w.y, a.y);
            a.z = fmaf(v, w.z, a.z);
            a.w = fmaf(v, w.w, a.w);
        }
        a.x = fmaxf(a.x, 0.f); a.y = fmaxf(a.y, 0.f);
        a.z = fmaxf(a.z, 0.f); a.w = fmaxf(a.w, 0.f);
        red_add_v4(g_agg + j * HD + lane * 4, a);
    }
}

// ---------------- edge stage: fi = relu(P[src]+Q[dst]); scatter into aggr[dst] ----------------
__global__ void edge_kernel(const int* __restrict__ ei) {
    int t = blockIdx.x * blockDim.x + threadIdx.x;
    int lane = t & 15;
    int group = t >> 4;
    int ngroups = (gridDim.x * blockDim.x) >> 4;
    for (int e = group; e < NE; e += ngroups) {
        int s = ei[e];
        int d = ei[NE + e];
        float4 a = ((const float4*)(g_P + s * HD))[lane];
        float4 b = ((const float4*)(g_Q + d * HD))[lane];
        a.x = fmaxf(a.x + b.x, 0.f);
        a.y = fmaxf(a.y + b.y, 0.f);
        a.z = fmaxf(a.z + b.z, 0.f);
        a.w = fmaxf(a.w + b.w, 0.f);
        red_add_v4(g_aggr + d * HD + lane * 4, a);
    }
}

// ---------------- pooling ----------------
__global__ void pool_kernel(const int* __restrict__ batch) {
    int t = blockIdx.x * blockDim.x + threadIdx.x;
    int lane = t & 15;
    int n = t >> 4;
    if (n >= NN) return;
    int b = batch[n];
    float4 v = ((const float4*)(g_h + n * HD))[lane];
    red_add_v4(g_pool + b * HD + lane * 4, v);
    if (lane == 0) atomicAdd(&g_gcnt[b], 1.0f);
}

// ---------------- final small MLP ----------------
__global__ void final_kernel(const float* __restrict__ Wo1,
                             const float* __restrict__ bo1,
                             const float* __restrict__ Wo2,
                             const float* __restrict__ bo2,
                             float* __restrict__ out) {
    __shared__ float pooled[HD];
    __shared__ float t1[HD];
    int b = blockIdx.x;
    int t = threadIdx.x;  // 64 threads
    float cnt = fmaxf(g_gcnt[b], 1.0f);
    pooled[t] = fmaxf(g_pool[b * HD + t] / cnt, 0.f);
    __syncthreads();
    float acc = bo1[t];
#pragma unroll 8
    for (int k = 0; k < HD; k++) acc = fmaf(pooled[k], Wo1[k * HD + t], acc);
    t1[t] = fmaxf(acc, 0.f);
    __syncthreads();
    if (t < OUTD) {
        float a2 = bo2[t];
#pragma unroll 8
        for (int k = 0; k < HD; k++) a2 = fmaf(t1[k], Wo2[k * OUTD + t], a2);
        out[b * OUTD + t] = a2;
    }
}

// ---------------- host orchestration ----------------
extern "C" void kernel_launch(void* const* d_in, const int* in_sizes, int n_in,
                              void* d_out, int out_size) {
    (void)in_sizes; (void)n_in; (void)out_size;
    const float* x   = (const float*)d_in[0];
    const float* rbf = (const float*)d_in[1];
    const float* cbf = (const float*)d_in[2];
    const float* W1  = (const float*)d_in[3];
    const float* b1  = (const float*)d_in[4];
    const float* W2  = (const float*)d_in[5];
    const float* b2  = (const float*)d_in[6];
    const float* Wn1 = (const float*)d_in[7];
    const float* bn1 = (const float*)d_in[8];
    const float* Wn2 = (const float*)d_in[9];
    const float* bn2 = (const float*)d_in[10];
    const float* Wo1 = (const float*)d_in[11];
    const float* bo1 = (const float*)d_in[12];
    const float* Wo2 = (const float*)d_in[13];
    const float* bo2 = (const float*)d_in[14];
    const int* ei    = (const int*)d_in[15];
    const int* k_idx = (const int*)d_in[16];
    const int* j_idx = (const int*)d_in[17];
    const int* batch = (const int*)d_in[18];
    float* out = (float*)d_out;

    zero_init_kernel<<<(NN * HD / 4 + 255) / 256, 256>>>();
    compact_kernel<<<(NT + 255) / 256, 256>>>(j_idx);
    rbfproj_all_kernel<<<dim3(NN / 16, 3), 256>>>(rbf, W1, b1);
    proj3_kernel<<<NN / 64, 256>>>(x, W1, W2, Wn1);

    for (int l = 0; l < 3; l++) {
        triplet_kernel<<<1024, 256>>>(cbf, k_idx, j_idx, W1, l);
        qproj_kernel<<<NN / 64, 256>>>(W2 + l * 128 * HD + 64 * HD, b2 + l * HD);
        edge_kernel<<<4096, 256>>>(ei);
        int nl = (l < 2) ? (l + 1) : l;
        node_update_kernel<<<NN / 64, 256>>>(
            Wn1 + l * 128 * HD + 64 * HD, bn1 + l * HD,
            Wn2 + l * 64 * HD, bn2 + l * HD,
            W1 + nl * 76 * HD, W2 + nl * 128 * HD, Wn1 + nl * 128 * HD,
            (l < 2) ? 1 : 0);
    }

    pool_kernel<<<(NN * 16 + 255) / 256, 256>>>(batch);
    final_kernel<<<NBATCH, 64>>>(Wo1, bo1, Wo2, bo2, out);
}